// round 6
// baseline (speedup 1.0000x reference)
#include <cuda_runtime.h>
#include <math.h>
#include <stdint.h>

#define NB 8
#define NS 2048
#define ND 1024
#define NH1 512
#define NDH 128
#define NDV 512
#define NDOUT 512
#define NM (NB*NS)   // 16384

// scratch (device globals: allocation-free per harness rules)
__device__ float g_W12[ND*NDH];
__device__ float g_W46[ND*NDH];
__device__ float g_Q2[(size_t)NM*NDH];
__device__ float g_K3[(size_t)NM*NDH];
__device__ float g_Q3[(size_t)NM*NDV];
__device__ float g_ATTN[(size_t)NM*NDV];

// ---------------------------------------------------------------------------
// helpers
// ---------------------------------------------------------------------------
__device__ __forceinline__ float to_tf32(float x) {
    float r;
    asm("cvt.rna.tf32.f32 %0, %1;" : "=f"(r) : "f"(x));
    return r;
}
__device__ __forceinline__ float4 to_tf32_4(float4 v) {
    v.x = to_tf32(v.x); v.y = to_tf32(v.y);
    v.z = to_tf32(v.z); v.w = to_tf32(v.w);
    return v;
}
__device__ __forceinline__ uint32_t fbits(float x) { return __float_as_uint(x); }

// D += A@B  (m16n8k8, tf32, row.col)
__device__ __forceinline__ void mma8(float d[4], const uint32_t a[4],
                                     uint32_t b0, uint32_t b1) {
    asm volatile(
        "mma.sync.aligned.m16n8k8.row.col.f32.tf32.tf32.f32 "
        "{%0,%1,%2,%3},{%4,%5,%6,%7},{%8,%9},{%0,%1,%2,%3};"
        : "+f"(d[0]), "+f"(d[1]), "+f"(d[2]), "+f"(d[3])
        : "r"(a[0]), "r"(a[1]), "r"(a[2]), "r"(a[3]), "r"(b0), "r"(b1));
}

// ---------------------------------------------------------------------------
// TF32 GEMM body: C[*,N] tile at (brow,bcol) = (A (+A2)) @ (B (+B2))
// row-major; tile 128x128, BK=16, 256 threads = 8 warps (2m x 4n)
// ---------------------------------------------------------------------------
#define APITCH 136   // 136 % 32 == 8 -> conflict-free (8*lr + lq) fragment pattern

template<bool FUSEA, bool FUSEB>
__device__ __forceinline__ void gemm_body(
    float (*As)[16][APITCH], float (*Bs)[16][APITCH],
    const float* __restrict__ A, const float* __restrict__ A2,
    const float* __restrict__ Bm, const float* __restrict__ B2,
    float* __restrict__ C, int N, int K, int brow, int bcol)
{
    const int tid  = threadIdx.x;
    const int lane = tid & 31;
    const int w    = tid >> 5;
    const int lq   = lane >> 2;     // 0..7
    const int lr   = lane & 3;      // 0..3
    const int wm   = w >> 2;        // 0..1
    const int wn   = w & 3;         // 0..3

    // A-load mapping: 512 float4s; thread handles f = tid, tid+256
    const int ar0 = tid >> 2,         akc0 = (tid & 3) << 2;
    const int ar1 = (tid + 256) >> 2, akc1 = ((tid + 256) & 3) << 2;
    // B-load mapping
    const int bk0 = tid >> 5,         bnc0 = (tid & 31) << 2;
    const int bk1 = (tid + 256) >> 5, bnc1 = ((tid + 256) & 31) << 2;

    const float* Ap0  = A  + (size_t)(brow + ar0) * K + akc0;
    const float* Ap1  = A  + (size_t)(brow + ar1) * K + akc1;
    const float* A2p0 = FUSEA ? (A2 + (size_t)(brow + ar0) * K + akc0) : nullptr;
    const float* A2p1 = FUSEA ? (A2 + (size_t)(brow + ar1) * K + akc1) : nullptr;
    const float* Bp0  = Bm + (size_t)bk0 * N + bcol + bnc0;
    const float* Bp1  = Bm + (size_t)bk1 * N + bcol + bnc1;
    const float* B2p0 = FUSEB ? (B2 + (size_t)bk0 * N + bcol + bnc0) : nullptr;
    const float* B2p1 = FUSEB ? (B2 + (size_t)bk1 * N + bcol + bnc1) : nullptr;

    float acc[4][4][4];
#pragma unroll
    for (int mt = 0; mt < 4; mt++)
#pragma unroll
        for (int nt = 0; nt < 4; nt++)
#pragma unroll
            for (int i = 0; i < 4; i++) acc[mt][nt][i] = 0.f;

    const int nk = K / 16;

    // prologue: stage 0 into buf 0
    {
        float4 a0 = *(const float4*)Ap0;
        float4 a1 = *(const float4*)Ap1;
        if (FUSEA) {
            float4 e0 = *(const float4*)A2p0, e1 = *(const float4*)A2p1;
            a0.x += e0.x; a0.y += e0.y; a0.z += e0.z; a0.w += e0.w;
            a1.x += e1.x; a1.y += e1.y; a1.z += e1.z; a1.w += e1.w;
        }
        a0 = to_tf32_4(a0); a1 = to_tf32_4(a1);
        As[0][akc0+0][ar0] = a0.x; As[0][akc0+1][ar0] = a0.y;
        As[0][akc0+2][ar0] = a0.z; As[0][akc0+3][ar0] = a0.w;
        As[0][akc1+0][ar1] = a1.x; As[0][akc1+1][ar1] = a1.y;
        As[0][akc1+2][ar1] = a1.z; As[0][akc1+3][ar1] = a1.w;
        float4 b0 = *(const float4*)Bp0;
        float4 b1 = *(const float4*)Bp1;
        if (FUSEB) {
            float4 e0 = *(const float4*)B2p0, e1 = *(const float4*)B2p1;
            b0.x += e0.x; b0.y += e0.y; b0.z += e0.z; b0.w += e0.w;
            b1.x += e1.x; b1.y += e1.y; b1.z += e1.z; b1.w += e1.w;
        }
        *(float4*)&Bs[0][bk0][bnc0] = to_tf32_4(b0);
        *(float4*)&Bs[0][bk1][bnc1] = to_tf32_4(b1);
    }
    __syncthreads();

    for (int kt = 0; kt < nk; kt++) {
        const int buf = kt & 1;
        float4 pa0, pa1, pb0, pb1;
        const bool more = (kt + 1 < nk);
        if (more) {
            const int ko = (kt + 1) * 16;
            pa0 = *(const float4*)(Ap0 + ko);
            pa1 = *(const float4*)(Ap1 + ko);
            if (FUSEA) {
                float4 e0 = *(const float4*)(A2p0 + ko);
                float4 e1 = *(const float4*)(A2p1 + ko);
                pa0.x += e0.x; pa0.y += e0.y; pa0.z += e0.z; pa0.w += e0.w;
                pa1.x += e1.x; pa1.y += e1.y; pa1.z += e1.z; pa1.w += e1.w;
            }
            pb0 = *(const float4*)(Bp0 + (size_t)ko * N);
            pb1 = *(const float4*)(Bp1 + (size_t)ko * N);
            if (FUSEB) {
                float4 e0 = *(const float4*)(B2p0 + (size_t)ko * N);
                float4 e1 = *(const float4*)(B2p1 + (size_t)ko * N);
                pb0.x += e0.x; pb0.y += e0.y; pb0.z += e0.z; pb0.w += e0.w;
                pb1.x += e1.x; pb1.y += e1.y; pb1.z += e1.z; pb1.w += e1.w;
            }
        }

        // compute on buf
#pragma unroll
        for (int ks = 0; ks < 2; ks++) {
            const int k = ks * 8;
            uint32_t af[4][4], bf[4][2];
#pragma unroll
            for (int mt = 0; mt < 4; mt++) {
                const int bm = wm * 64 + mt * 16;
                af[mt][0] = fbits(As[buf][k + lr    ][bm + lq    ]);
                af[mt][1] = fbits(As[buf][k + lr    ][bm + lq + 8]);
                af[mt][2] = fbits(As[buf][k + 4 + lr][bm + lq    ]);
                af[mt][3] = fbits(As[buf][k + 4 + lr][bm + lq + 8]);
            }
#pragma unroll
            for (int nt = 0; nt < 4; nt++) {
                const int bn = wn * 32 + nt * 8;
                bf[nt][0] = fbits(Bs[buf][k + lr    ][bn + lq]);
                bf[nt][1] = fbits(Bs[buf][k + 4 + lr][bn + lq]);
            }
#pragma unroll
            for (int mt = 0; mt < 4; mt++)
#pragma unroll
                for (int nt = 0; nt < 4; nt++)
                    mma8(acc[mt][nt], af[mt], bf[nt][0], bf[nt][1]);
        }

        if (more) {
            const int nb = buf ^ 1;
            pa0 = to_tf32_4(pa0); pa1 = to_tf32_4(pa1);
            As[nb][akc0+0][ar0] = pa0.x; As[nb][akc0+1][ar0] = pa0.y;
            As[nb][akc0+2][ar0] = pa0.z; As[nb][akc0+3][ar0] = pa0.w;
            As[nb][akc1+0][ar1] = pa1.x; As[nb][akc1+1][ar1] = pa1.y;
            As[nb][akc1+2][ar1] = pa1.z; As[nb][akc1+3][ar1] = pa1.w;
            *(float4*)&Bs[nb][bk0][bnc0] = to_tf32_4(pb0);
            *(float4*)&Bs[nb][bk1][bnc1] = to_tf32_4(pb1);
            __syncthreads();
        }
    }

    // epilogue
#pragma unroll
    for (int mt = 0; mt < 4; mt++) {
        const int r0 = brow + wm * 64 + mt * 16 + lq;
#pragma unroll
        for (int nt = 0; nt < 4; nt++) {
            const int col = bcol + wn * 32 + nt * 8 + lr * 2;
            *(float2*)(C + (size_t)r0 * N + col)       = make_float2(acc[mt][nt][0], acc[mt][nt][1]);
            *(float2*)(C + (size_t)(r0 + 8) * N + col) = make_float2(acc[mt][nt][2], acc[mt][nt][3]);
        }
    }
}

// ---- merged GEMM launches ----
// weight prep: W12 = w1@w2 (y=0), W46 = w4@w6 (y=1). grid(8,2)
__global__ __launch_bounds__(256, 2) void weight_prep_kernel(
    const float* __restrict__ w1, const float* __restrict__ w2, float* __restrict__ W12,
    const float* __restrict__ w4, const float* __restrict__ w6, float* __restrict__ W46)
{
    __shared__ float As[2][16][APITCH];
    __shared__ float Bs[2][16][APITCH];
    if (blockIdx.y == 0)
        gemm_body<false,false>(As, Bs, w1, nullptr, w2, nullptr, W12, NDH, NH1, blockIdx.x*128, 0);
    else
        gemm_body<false,false>(As, Bs, w4, nullptr, w6, nullptr, W46, NDH, NH1, blockIdx.x*128, 0);
}

// projections: y=0 -> Q2 = q@W12; y=1 -> K3 = k@W46; y=2..5 -> Q3 = q@w3. grid(128,6)
__global__ __launch_bounds__(256, 2) void proj_kernel(
    const float* __restrict__ q, const float* __restrict__ k,
    const float* __restrict__ W12, const float* __restrict__ W46,
    const float* __restrict__ w3,
    float* __restrict__ Q2, float* __restrict__ K3, float* __restrict__ Q3)
{
    __shared__ float As[2][16][APITCH];
    __shared__ float Bs[2][16][APITCH];
    const int y = blockIdx.y;
    if (y == 0)
        gemm_body<false,false>(As, Bs, q, nullptr, W12, nullptr, Q2, NDH, ND, blockIdx.x*128, 0);
    else if (y == 1)
        gemm_body<false,false>(As, Bs, k, nullptr, W46, nullptr, K3, NDH, ND, blockIdx.x*128, 0);
    else
        gemm_body<false,false>(As, Bs, q, nullptr, w3, nullptr, Q3, NDV, ND, blockIdx.x*128, (y-2)*128);
}

// final: out = (ATTN + Q3) @ (w7_top + w7_bot). grid(128,4)
__global__ __launch_bounds__(256, 2) void final_kernel(
    const float* __restrict__ ATTN, const float* __restrict__ Q3,
    const float* __restrict__ w7, float* __restrict__ out)
{
    __shared__ float As[2][16][APITCH];
    __shared__ float Bs[2][16][APITCH];
    gemm_body<true,true>(As, Bs, ATTN, Q3, w7, w7 + (size_t)NDV*NDOUT, out,
                         NDOUT, NDV, blockIdx.x*128, blockIdx.y*128);
}

// ---------------------------------------------------------------------------
// Flash attention (causal), tf32 mma. BM=BN=64, DH=128.
// DV SPLIT: grid.z=2, each CTA computes 256 of 512 V columns (QK+softmax dup).
// V double-buffered; K+V for iter kt+1 prefetched via cp.async during PV of kt.
// 512 threads. QK warps: 4m x 4n (16x16); PV warps: 2m x 8n (32x32).
// ---------------------------------------------------------------------------
#define QPITCH 132    // q*132+r: 132%32=4 -> (4lq+lr) distinct
#define PPITCH 68     // 68%32=4
#define VPITCH2 264   // r*264+c: 264%32=8 -> (8lr+lq) distinct
#define VHALF 256

__global__ __launch_bounds__(512) void flash_attn_tf32(
    const float* __restrict__ Q2, const float* __restrict__ K3,
    const float* __restrict__ V, float* __restrict__ O)
{
    extern __shared__ float sm[];
    float* Qs   = sm;                       // [64][132]
    float* Ks   = Qs + 64 * QPITCH;         // [64][132]
    float* Ps   = Ks + 64 * QPITCH;         // [64][68]
    float* Vs0  = Ps + 64 * PPITCH;         // [64][264] buf 0
    float* Vs1  = Vs0 + 64 * VPITCH2;       // [64][264] buf 1
    float* mrow = Vs1 + 64 * VPITCH2;       // [64]
    float* lrow = mrow + 64;                // [64]
    float* arow = lrow + 64;                // [64]

    const int b   = blockIdx.y;
    const int z   = blockIdx.z;             // DV half: cols [z*256, z*256+256)
    const int qt  = (int)gridDim.x - 1 - (int)blockIdx.x;  // long blocks first
    const int q0  = qt * 64;
    const int tid = threadIdx.x;
    const int lane = tid & 31, w = tid >> 5;    // w: 0..15
    const int lq = lane >> 2, lr = lane & 3;
    const int wmQ = w >> 2, wnQ = w & 3;   // QK: 4m x 4n
    const int wmP = w >> 3, wnP = w & 7;   // PV: 2m x 8n
    const float scale = 0.088388347648318447f;  // 1/sqrt(128)
    const uint32_t ksmem  = (uint32_t)__cvta_generic_to_shared(Ks);
    const uint32_t vsmem0 = (uint32_t)__cvta_generic_to_shared(Vs0);
    const uint32_t vsmem1 = (uint32_t)__cvta_generic_to_shared(Vs1);
    const float* Vbase = V + z * VHALF;

    // load Q tile (tf32, rna) — once
    const float* Qg = Q2 + ((size_t)b * NS + q0) * NDH;
    for (int f = tid; f < 2048; f += 512) {
        int row = f >> 5, kc = (f & 31) << 2;
        *(float4*)&Qs[row * QPITCH + kc] = to_tf32_4(*(const float4*)(Qg + row * NDH + kc));
    }
    if (tid < 64) { mrow[tid] = -1e30f; lrow[tid] = 0.f; }

    // prologue prefetch: K_0 -> Ks, V_0 -> buf0  (one group)
    {
        const float* Kg = K3 + ((size_t)b * NS) * NDH;
#pragma unroll
        for (int f = tid; f < 2048; f += 512) {
            int row = f >> 5, kc = (f & 31) << 2;
            uint32_t dst = ksmem + (uint32_t)(row * QPITCH + kc) * 4u;
            asm volatile("cp.async.cg.shared.global [%0], [%1], 16;\n"
                         :: "r"(dst), "l"(Kg + (size_t)row * NDH + kc));
        }
        const float* Vg = Vbase + ((size_t)b * NS) * NDV;
#pragma unroll
        for (int f = tid; f < 4096; f += 512) {
            int row = f >> 6, nc = (f & 63) << 2;
            uint32_t dst = vsmem0 + (uint32_t)(row * VPITCH2 + nc) * 4u;
            asm volatile("cp.async.cg.shared.global [%0], [%1], 16;\n"
                         :: "r"(dst), "l"(Vg + (size_t)row * NDV + nc));
        }
        asm volatile("cp.async.commit_group;\n" ::: "memory");
    }

    float oacc[2][4][4];
#pragma unroll
    for (int mt = 0; mt < 2; mt++)
#pragma unroll
        for (int nt = 0; nt < 4; nt++)
#pragma unroll
            for (int i = 0; i < 4; i++) oacc[mt][nt][i] = 0.f;

    for (int kt = 0; kt <= qt; kt++) {
        const int k0 = kt * 64;

        // K_kt + V_kt arrived (issued one iteration ago)
        asm volatile("cp.async.wait_group 0;\n" ::: "memory");
        __syncthreads();

        // ---- S = Q @ K^T  (warp: 16 rows x 16 cols) ----
        float sacc[2][4];
#pragma unroll
        for (int nt = 0; nt < 2; nt++)
#pragma unroll
            for (int i = 0; i < 4; i++) sacc[nt][i] = 0.f;

#pragma unroll
        for (int ks = 0; ks < 16; ks++) {
            const int k = ks * 8;
            uint32_t af[4];
            const int rq = (wmQ * 16 + lq) * QPITCH;
            af[0] = fbits(Qs[rq            + k + lr]);
            af[1] = fbits(Qs[rq + 8*QPITCH + k + lr]);
            af[2] = fbits(Qs[rq            + k + 4 + lr]);
            af[3] = fbits(Qs[rq + 8*QPITCH + k + 4 + lr]);
#pragma unroll
            for (int nt = 0; nt < 2; nt++) {
                const int rk = (wnQ * 16 + nt * 8 + lq) * QPITCH;
                uint32_t b0 = fbits(Ks[rk + k + lr]);
                uint32_t b1 = fbits(Ks[rk + k + 4 + lr]);
                mma8(sacc[nt], af, b0, b1);
            }
        }
        // scale + causal mask + store to Ps (fp32)
        {
            const bool diag = (kt == qt);
            const int rloc0 = wmQ * 16 + lq;
            const int grow0 = q0 + rloc0, grow1 = grow0 + 8;
#pragma unroll
            for (int nt = 0; nt < 2; nt++) {
                const int col = wnQ * 16 + nt * 8 + lr * 2;
                const int gc0 = k0 + col, gc1 = gc0 + 1;
                float v0 = sacc[nt][0] * scale;
                float v1 = sacc[nt][1] * scale;
                float v2 = sacc[nt][2] * scale;
                float v3 = sacc[nt][3] * scale;
                if (diag) {
                    if (gc0 > grow0) v0 = -1e30f;
                    if (gc1 > grow0) v1 = -1e30f;
                    if (gc0 > grow1) v2 = -1e30f;
                    if (gc1 > grow1) v3 = -1e30f;
                }
                Ps[rloc0 * PPITCH + col]           = v0;
                Ps[rloc0 * PPITCH + col + 1]       = v1;
                Ps[(rloc0 + 8) * PPITCH + col]     = v2;
                Ps[(rloc0 + 8) * PPITCH + col + 1] = v3;
            }
        }
        __syncthreads();

        // ---- online softmax on Ps (8 threads/row, 8 cols each) ----
        {
            const int row = tid >> 3, g = tid & 7;
            float mx = -1e30f;
#pragma unroll
            for (int c = 0; c < 8; c++) mx = fmaxf(mx, Ps[row * PPITCH + g * 8 + c]);
            mx = fmaxf(mx, __shfl_xor_sync(0xffffffffu, mx, 1));
            mx = fmaxf(mx, __shfl_xor_sync(0xffffffffu, mx, 2));
            mx = fmaxf(mx, __shfl_xor_sync(0xffffffffu, mx, 4));
            const float mold = mrow[row];
            const float mnew = fmaxf(mold, mx);
            const float al   = __expf(mold - mnew);
            float sum = 0.f;
#pragma unroll
            for (int c = 0; c < 8; c++) {
                const int idx = row * PPITCH + g * 8 + c;
                float p = __expf(Ps[idx] - mnew);
                Ps[idx] = to_tf32(p);
                sum += p;
            }
            sum += __shfl_xor_sync(0xffffffffu, sum, 1);
            sum += __shfl_xor_sync(0xffffffffu, sum, 2);
            sum += __shfl_xor_sync(0xffffffffu, sum, 4);
            if (g == 0) {
                mrow[row] = mnew;
                lrow[row] = lrow[row] * al + sum;
                arow[row] = al;
            }
        }
        __syncthreads();   // softmax writes + arow visible; Ks QK-reads complete

        // ---- prefetch K_{kt+1} -> Ks (safe: S extracted) and V_{kt+1} -> other buf
        if (kt < qt) {
            const int kn = k0 + 64;
            const float* Kg = K3 + ((size_t)b * NS + kn) * NDH;
#pragma unroll
            for (int f = tid; f < 2048; f += 512) {
                int row = f >> 5, kc = (f & 31) << 2;
                uint32_t dst = ksmem + (uint32_t)(row * QPITCH + kc) * 4u;
                asm volatile("cp.async.cg.shared.global [%0], [%1], 16;\n"
                             :: "r"(dst), "l"(Kg + (size_t)row * NDH + kc));
            }
            const uint32_t vdstb = ((kt + 1) & 1) ? vsmem1 : vsmem0;
            const float* Vg = Vbase + ((size_t)b * NS + kn) * NDV;
#pragma unroll
            for (int f = tid; f < 4096; f += 512) {
                int row = f >> 6, nc = (f & 63) << 2;
                uint32_t dst = vdstb + (uint32_t)(row * VPITCH2 + nc) * 4u;
                asm volatile("cp.async.cg.shared.global [%0], [%1], 16;\n"
                             :: "r"(dst), "l"(Vg + (size_t)row * NDV + nc));
            }
            asm volatile("cp.async.commit_group;\n" ::: "memory");
        }

        // ---- rescale O accumulators, then O += P @ V  (overlaps with prefetch)
        {
            const float* Vsc = (kt & 1) ? Vs1 : Vs0;
            const int rb = wmP * 32;
            const float al00 = arow[rb + lq];
            const float al01 = arow[rb + lq + 8];
            const float al10 = arow[rb + 16 + lq];
            const float al11 = arow[rb + 16 + lq + 8];
#pragma unroll
            for (int nt = 0; nt < 4; nt++) {
                oacc[0][nt][0] *= al00; oacc[0][nt][1] *= al00;
                oacc[0][nt][2] *= al01; oacc[0][nt][3] *= al01;
                oacc[1][nt][0] *= al10; oacc[1][nt][1] *= al10;
                oacc[1][nt][2] *= al11; oacc[1][nt][3] *= al11;
            }
#pragma unroll
            for (int ks = 0; ks < 8; ks++) {
                const int k = ks * 8;
                uint32_t af[2][4];
#pragma unroll
                for (int mt = 0; mt < 2; mt++) {
                    const int rp = (rb + mt * 16 + lq) * PPITCH;
                    af[mt][0] = fbits(Ps[rp             + k + lr]);
                    af[mt][1] = fbits(Ps[rp + 8*PPITCH  + k + lr]);
                    af[mt][2] = fbits(Ps[rp             + k + 4 + lr]);
                    af[mt][3] = fbits(Ps[rp + 8*PPITCH  + k + 4 + lr]);
                }
#pragma unroll
                for (int nt = 0; nt < 4; nt++) {
                    const int cb = wnP * 32 + nt * 8 + lq;
                    uint32_t b0 = fbits(Vsc[(k + lr) * VPITCH2 + cb]);
                    uint32_t b1 = fbits(Vsc[(k + 4 + lr) * VPITCH2 + cb]);
                    mma8(oacc[0][nt], af[0], b0, b1);
                    mma8(oacc[1][nt], af[1], b0, b1);
                }
            }
        }
    }

    __syncthreads();
    // epilogue: normalize and store.  comp = 1 + 2^-12 cancels the mean
    // downward bias of feeding raw fp32 V bits to the tf32 mma (truncation).
    {
        const float comp = 1.000244140625f;
        const int rb = wmP * 32;
        float li[2][2];
        li[0][0] = comp / lrow[rb + lq];
        li[0][1] = comp / lrow[rb + lq + 8];
        li[1][0] = comp / lrow[rb + 16 + lq];
        li[1][1] = comp / lrow[rb + 16 + lq + 8];
#pragma unroll
        for (int mt = 0; mt < 2; mt++) {
            const int gr = q0 + rb + mt * 16 + lq;
#pragma unroll
            for (int nt = 0; nt < 4; nt++) {
                const int col = z * VHALF + wnP * 32 + nt * 8 + lr * 2;
                *(float2*)(O + ((size_t)b * NS + gr) * NDV + col) =
                    make_float2(oacc[mt][nt][0] * li[mt][0], oacc[mt][nt][1] * li[mt][0]);
                *(float2*)(O + ((size_t)b * NS + gr + 8) * NDV + col) =
                    make_float2(oacc[mt][nt][2] * li[mt][1], oacc[mt][nt][3] * li[mt][1]);
            }
        }
    }
}

// ---------------------------------------------------------------------------
extern "C" void kernel_launch(void* const* d_in, const int* in_sizes, int n_in,
                              void* d_out, int out_size)
{
    const float* q  = (const float*)d_in[0];
    const float* k  = (const float*)d_in[1];
    const float* v  = (const float*)d_in[2];
    const float* w1 = (const float*)d_in[3];
    const float* w2 = (const float*)d_in[4];
    const float* w3 = (const float*)d_in[5];
    const float* w4 = (const float*)d_in[6];
    const float* w6 = (const float*)d_in[7];
    const float* w7 = (const float*)d_in[8];
    float* out = (float*)d_out;

    // cache symbol addresses + one-time attribute setup across calls
    static float *W12 = nullptr, *W46, *Q2, *K3, *Q3, *ATTN;
    static bool init_done = false;
    if (!init_done) {
        cudaGetSymbolAddress((void**)&W12,  g_W12);
        cudaGetSymbolAddress((void**)&W46,  g_W46);
        cudaGetSymbolAddress((void**)&Q2,   g_Q2);
        cudaGetSymbolAddress((void**)&K3,   g_K3);
        cudaGetSymbolAddress((void**)&Q3,   g_Q3);
        cudaGetSymbolAddress((void**)&ATTN, g_ATTN);
        size_t smem_attr = (size_t)(2*64*QPITCH + 64*PPITCH + 2*64*VPITCH2 + 192) * sizeof(float);
        cudaFuncSetAttribute(flash_attn_tf32, cudaFuncAttributeMaxDynamicSharedMemorySize, (int)smem_attr);
        init_done = true;
    }

    // 1) weight prep:  W12 = w1@w2, W46 = w4@w6   (one launch, grid 8x2)
    weight_prep_kernel<<<dim3(ND/128, 2), 256>>>(w1, w2, W12, w4, w6, W46);

    // 2) all projections in one launch: Q2 = q@W12, K3 = k@W46, Q3 = q@w3
    proj_kernel<<<dim3(NM/128, 6), 256>>>(q, k, W12, W46, w3, Q2, K3, Q3);

    // 3) causal flash attention (tf32, DV split x2, V double-buffered prefetch)
    size_t smem = (size_t)(2*64*QPITCH + 64*PPITCH + 2*64*VPITCH2 + 192) * sizeof(float);
    flash_attn_tf32<<<dim3(NS/64, NB, 2), 512, smem>>>(Q2, K3, v, ATTN);

    // 4) final: out = (ATTN + Q3) @ (w7_top + w7_bot)   (wsum fused into B-stage)
    final_kernel<<<dim3(NM/128, NDOUT/128), 256>>>(ATTN, Q3, w7, out);
}

// round 7
// speedup vs baseline: 1.9385x; 1.9385x over previous
#include <cuda_runtime.h>
#include <cuda_bf16.h>
#include <math.h>
#include <stdint.h>

#define NB 8
#define NS 2048
#define ND 1024
#define NH1 512
#define NDH 128
#define NDV 512
#define NDOUT 512
#define NM (NB*NS)   // 16384

// scratch (device globals: allocation-free per harness rules)
__device__ float g_W12[ND*NDH];
__device__ float g_W46[ND*NDH];
__device__ __nv_bfloat16 g_Q2h[(size_t)NM*NDH];
__device__ __nv_bfloat16 g_K3h[(size_t)NM*NDH];
__device__ __nv_bfloat16 g_Vt[(size_t)NB*NDV*NS];   // [b][dv][seq]
__device__ float g_Q3[(size_t)NM*NDV];
__device__ float g_ATTN[(size_t)NM*NDV];

// ---------------------------------------------------------------------------
// helpers
// ---------------------------------------------------------------------------
__device__ __forceinline__ float to_tf32(float x) {
    float r;
    asm("cvt.rna.tf32.f32 %0, %1;" : "=f"(r) : "f"(x));
    return r;
}
__device__ __forceinline__ float4 to_tf32_4(float4 v) {
    v.x = to_tf32(v.x); v.y = to_tf32(v.y);
    v.z = to_tf32(v.z); v.w = to_tf32(v.w);
    return v;
}
__device__ __forceinline__ uint32_t fbits(float x) { return __float_as_uint(x); }

// pack two floats -> bf16x2 (lo = first arg)
__device__ __forceinline__ uint32_t bfpack(float lo, float hi) {
    uint32_t r;
    asm("cvt.rn.bf16x2.f32 %0, %1, %2;" : "=r"(r) : "f"(hi), "f"(lo));
    return r;
}
__device__ __forceinline__ float bflo(uint32_t w) { return __uint_as_float(w << 16); }
__device__ __forceinline__ float bfhi(uint32_t w) { return __uint_as_float(w & 0xffff0000u); }

// D += A@B  (m16n8k8, tf32, row.col)
__device__ __forceinline__ void mma8(float d[4], const uint32_t a[4],
                                     uint32_t b0, uint32_t b1) {
    asm volatile(
        "mma.sync.aligned.m16n8k8.row.col.f32.tf32.tf32.f32 "
        "{%0,%1,%2,%3},{%4,%5,%6,%7},{%8,%9},{%0,%1,%2,%3};"
        : "+f"(d[0]), "+f"(d[1]), "+f"(d[2]), "+f"(d[3])
        : "r"(a[0]), "r"(a[1]), "r"(a[2]), "r"(a[3]), "r"(b0), "r"(b1));
}
// D += A@B  (m16n8k16, bf16, row.col)
__device__ __forceinline__ void mma16(float d[4], const uint32_t a[4],
                                      uint32_t b0, uint32_t b1) {
    asm volatile(
        "mma.sync.aligned.m16n8k16.row.col.f32.bf16.bf16.f32 "
        "{%0,%1,%2,%3},{%4,%5,%6,%7},{%8,%9},{%0,%1,%2,%3};"
        : "+f"(d[0]), "+f"(d[1]), "+f"(d[2]), "+f"(d[3])
        : "r"(a[0]), "r"(a[1]), "r"(a[2]), "r"(a[3]), "r"(b0), "r"(b1));
}

// ---------------------------------------------------------------------------
// TF32 GEMM body: C tile at (brow,bcol) = (A (+A2)) @ (B (+B2))
// row-major; tile 128x128, BK=16, 256 threads = 8 warps (2m x 4n)
// BF16OUT: C is __nv_bfloat16* (packed pair stores)
// ---------------------------------------------------------------------------
#define APITCH 136   // 136 % 32 == 8 -> conflict-free fragment pattern

template<bool FUSEA, bool FUSEB, bool BF16OUT>
__device__ __forceinline__ void gemm_body(
    float (*As)[16][APITCH], float (*Bs)[16][APITCH],
    const float* __restrict__ A, const float* __restrict__ A2,
    const float* __restrict__ Bm, const float* __restrict__ B2,
    void* __restrict__ Cv, int N, int K, int brow, int bcol)
{
    const int tid  = threadIdx.x;
    const int lane = tid & 31;
    const int w    = tid >> 5;
    const int lq   = lane >> 2;
    const int lr   = lane & 3;
    const int wm   = w >> 2;
    const int wn   = w & 3;

    const int ar0 = tid >> 2,         akc0 = (tid & 3) << 2;
    const int ar1 = (tid + 256) >> 2, akc1 = ((tid + 256) & 3) << 2;
    const int bk0 = tid >> 5,         bnc0 = (tid & 31) << 2;
    const int bk1 = (tid + 256) >> 5, bnc1 = ((tid + 256) & 31) << 2;

    const float* Ap0  = A  + (size_t)(brow + ar0) * K + akc0;
    const float* Ap1  = A  + (size_t)(brow + ar1) * K + akc1;
    const float* A2p0 = FUSEA ? (A2 + (size_t)(brow + ar0) * K + akc0) : nullptr;
    const float* A2p1 = FUSEA ? (A2 + (size_t)(brow + ar1) * K + akc1) : nullptr;
    const float* Bp0  = Bm + (size_t)bk0 * N + bcol + bnc0;
    const float* Bp1  = Bm + (size_t)bk1 * N + bcol + bnc1;
    const float* B2p0 = FUSEB ? (B2 + (size_t)bk0 * N + bcol + bnc0) : nullptr;
    const float* B2p1 = FUSEB ? (B2 + (size_t)bk1 * N + bcol + bnc1) : nullptr;

    float acc[4][4][4];
#pragma unroll
    for (int mt = 0; mt < 4; mt++)
#pragma unroll
        for (int nt = 0; nt < 4; nt++)
#pragma unroll
            for (int i = 0; i < 4; i++) acc[mt][nt][i] = 0.f;

    const int nk = K / 16;

    {
        float4 a0 = *(const float4*)Ap0;
        float4 a1 = *(const float4*)Ap1;
        if (FUSEA) {
            float4 e0 = *(const float4*)A2p0, e1 = *(const float4*)A2p1;
            a0.x += e0.x; a0.y += e0.y; a0.z += e0.z; a0.w += e0.w;
            a1.x += e1.x; a1.y += e1.y; a1.z += e1.z; a1.w += e1.w;
        }
        a0 = to_tf32_4(a0); a1 = to_tf32_4(a1);
        As[0][akc0+0][ar0] = a0.x; As[0][akc0+1][ar0] = a0.y;
        As[0][akc0+2][ar0] = a0.z; As[0][akc0+3][ar0] = a0.w;
        As[0][akc1+0][ar1] = a1.x; As[0][akc1+1][ar1] = a1.y;
        As[0][akc1+2][ar1] = a1.z; As[0][akc1+3][ar1] = a1.w;
        float4 b0 = *(const float4*)Bp0;
        float4 b1 = *(const float4*)Bp1;
        if (FUSEB) {
            float4 e0 = *(const float4*)B2p0, e1 = *(const float4*)B2p1;
            b0.x += e0.x; b0.y += e0.y; b0.z += e0.z; b0.w += e0.w;
            b1.x += e1.x; b1.y += e1.y; b1.z += e1.z; b1.w += e1.w;
        }
        *(float4*)&Bs[0][bk0][bnc0] = to_tf32_4(b0);
        *(float4*)&Bs[0][bk1][bnc1] = to_tf32_4(b1);
    }
    __syncthreads();

    for (int kt = 0; kt < nk; kt++) {
        const int buf = kt & 1;
        float4 pa0, pa1, pb0, pb1;
        const bool more = (kt + 1 < nk);
        if (more) {
            const int ko = (kt + 1) * 16;
            pa0 = *(const float4*)(Ap0 + ko);
            pa1 = *(const float4*)(Ap1 + ko);
            if (FUSEA) {
                float4 e0 = *(const float4*)(A2p0 + ko);
                float4 e1 = *(const float4*)(A2p1 + ko);
                pa0.x += e0.x; pa0.y += e0.y; pa0.z += e0.z; pa0.w += e0.w;
                pa1.x += e1.x; pa1.y += e1.y; pa1.z += e1.z; pa1.w += e1.w;
            }
            pb0 = *(const float4*)(Bp0 + (size_t)ko * N);
            pb1 = *(const float4*)(Bp1 + (size_t)ko * N);
            if (FUSEB) {
                float4 e0 = *(const float4*)(B2p0 + (size_t)ko * N);
                float4 e1 = *(const float4*)(B2p1 + (size_t)ko * N);
                pb0.x += e0.x; pb0.y += e0.y; pb0.z += e0.z; pb0.w += e0.w;
                pb1.x += e1.x; pb1.y += e1.y; pb1.z += e1.z; pb1.w += e1.w;
            }
        }

#pragma unroll
        for (int ks = 0; ks < 2; ks++) {
            const int k = ks * 8;
            uint32_t af[4][4], bf[4][2];
#pragma unroll
            for (int mt = 0; mt < 4; mt++) {
                const int bm = wm * 64 + mt * 16;
                af[mt][0] = fbits(As[buf][k + lr    ][bm + lq    ]);
                af[mt][1] = fbits(As[buf][k + lr    ][bm + lq + 8]);
                af[mt][2] = fbits(As[buf][k + 4 + lr][bm + lq    ]);
                af[mt][3] = fbits(As[buf][k + 4 + lr][bm + lq + 8]);
            }
#pragma unroll
            for (int nt = 0; nt < 4; nt++) {
                const int bn = wn * 32 + nt * 8;
                bf[nt][0] = fbits(Bs[buf][k + lr    ][bn + lq]);
                bf[nt][1] = fbits(Bs[buf][k + 4 + lr][bn + lq]);
            }
#pragma unroll
            for (int mt = 0; mt < 4; mt++)
#pragma unroll
                for (int nt = 0; nt < 4; nt++)
                    mma8(acc[mt][nt], af[mt], bf[nt][0], bf[nt][1]);
        }

        if (more) {
            const int nb = buf ^ 1;
            pa0 = to_tf32_4(pa0); pa1 = to_tf32_4(pa1);
            As[nb][akc0+0][ar0] = pa0.x; As[nb][akc0+1][ar0] = pa0.y;
            As[nb][akc0+2][ar0] = pa0.z; As[nb][akc0+3][ar0] = pa0.w;
            As[nb][akc1+0][ar1] = pa1.x; As[nb][akc1+1][ar1] = pa1.y;
            As[nb][akc1+2][ar1] = pa1.z; As[nb][akc1+3][ar1] = pa1.w;
            *(float4*)&Bs[nb][bk0][bnc0] = to_tf32_4(pb0);
            *(float4*)&Bs[nb][bk1][bnc1] = to_tf32_4(pb1);
            __syncthreads();
        }
    }

#pragma unroll
    for (int mt = 0; mt < 4; mt++) {
        const int r0 = brow + wm * 64 + mt * 16 + lq;
#pragma unroll
        for (int nt = 0; nt < 4; nt++) {
            const int col = bcol + wn * 32 + nt * 8 + lr * 2;
            if (BF16OUT) {
                uint32_t* C = (uint32_t*)Cv;
                C[((size_t)r0 * N + col) >> 1]       = bfpack(acc[mt][nt][0], acc[mt][nt][1]);
                C[((size_t)(r0 + 8) * N + col) >> 1] = bfpack(acc[mt][nt][2], acc[mt][nt][3]);
            } else {
                float* C = (float*)Cv;
                *(float2*)(C + (size_t)r0 * N + col)       = make_float2(acc[mt][nt][0], acc[mt][nt][1]);
                *(float2*)(C + (size_t)(r0 + 8) * N + col) = make_float2(acc[mt][nt][2], acc[mt][nt][3]);
            }
        }
    }
}

// ---- merged GEMM launches ----
__global__ __launch_bounds__(256, 2) void weight_prep_kernel(
    const float* __restrict__ w1, const float* __restrict__ w2, float* __restrict__ W12,
    const float* __restrict__ w4, const float* __restrict__ w6, float* __restrict__ W46)
{
    __shared__ float As[2][16][APITCH];
    __shared__ float Bs[2][16][APITCH];
    if (blockIdx.y == 0)
        gemm_body<false,false,false>(As, Bs, w1, nullptr, w2, nullptr, W12, NDH, NH1, blockIdx.x*128, 0);
    else
        gemm_body<false,false,false>(As, Bs, w4, nullptr, w6, nullptr, W46, NDH, NH1, blockIdx.x*128, 0);
}

// V transpose + bf16: Vt[b][n][s] = bf16(V[b][s][n])
__global__ __launch_bounds__(256) void vt_kernel(const float* __restrict__ V,
                                                 __nv_bfloat16* __restrict__ Vt)
{
    __shared__ float t[32][33];
    const int s0 = blockIdx.x * 32, n0 = blockIdx.y * 32, b = blockIdx.z;
    const int tx = threadIdx.x & 31, ty = threadIdx.x >> 5;   // 32 x 8
#pragma unroll
    for (int j = 0; j < 4; j++) {
        int s = s0 + ty + j * 8;
        t[ty + j * 8][tx] = V[((size_t)b * NS + s) * NDV + n0 + tx];
    }
    __syncthreads();
#pragma unroll
    for (int j = 0; j < 4; j++) {
        int n = n0 + ty + j * 8;
        Vt[((size_t)b * NDV + n) * NS + s0 + tx] = __float2bfloat16_rn(t[tx][ty + j * 8]);
    }
}

// projections: y=0 -> Q2h (bf16); y=1 -> K3h (bf16); y=2..5 -> Q3 (fp32)
__global__ __launch_bounds__(256, 2) void proj_kernel(
    const float* __restrict__ q, const float* __restrict__ k,
    const float* __restrict__ W12, const float* __restrict__ W46,
    const float* __restrict__ w3,
    __nv_bfloat16* __restrict__ Q2h, __nv_bfloat16* __restrict__ K3h,
    float* __restrict__ Q3)
{
    __shared__ float As[2][16][APITCH];
    __shared__ float Bs[2][16][APITCH];
    const int y = blockIdx.y;
    if (y == 0)
        gemm_body<false,false,true>(As, Bs, q, nullptr, W12, nullptr, Q2h, NDH, ND, blockIdx.x*128, 0);
    else if (y == 1)
        gemm_body<false,false,true>(As, Bs, k, nullptr, W46, nullptr, K3h, NDH, ND, blockIdx.x*128, 0);
    else
        gemm_body<false,false,false>(As, Bs, q, nullptr, w3, nullptr, Q3, NDV, ND, blockIdx.x*128, (y-2)*128);
}

// final: out = (ATTN + Q3) @ (w7_top + w7_bot). grid(128,4)
__global__ __launch_bounds__(256, 2) void final_kernel(
    const float* __restrict__ ATTN, const float* __restrict__ Q3,
    const float* __restrict__ w7, float* __restrict__ out)
{
    __shared__ float As[2][16][APITCH];
    __shared__ float Bs[2][16][APITCH];
    gemm_body<true,true,false>(As, Bs, ATTN, Q3, w7, w7 + (size_t)NDV*NDOUT, out,
                               NDOUT, NDV, blockIdx.x*128, blockIdx.y*128);
}

// ---------------------------------------------------------------------------
// Flash attention (causal), bf16 mma (m16n8k16). BM=BN=64, DH=128, DV=512.
// 512 threads. K,V double-buffered; 2-deep cp.async group pipeline.
// smem (bytes): Q[64][136]h @0, K0 @17408, K1 @34816, P[64][72]h @52224,
//               V0[512][72]h @61440, V1 @135168, stats(f32 x192) @208896.
// QK warps 4m x 4n (16x16); PV warps 2m x 8n (32x64).
// ---------------------------------------------------------------------------
#define OFF_K0 17408
#define OFF_K1 34816
#define OFF_P  52224
#define OFF_V0 61440
#define OFF_V1 135168
#define OFF_ST 208896
#define SMEM_ATTN 209664

__global__ __launch_bounds__(512) void flash_attn_bf16(
    const __nv_bfloat16* __restrict__ Q2h, const __nv_bfloat16* __restrict__ K3h,
    const __nv_bfloat16* __restrict__ Vt, float* __restrict__ O)
{
    extern __shared__ char smraw[];
    const uint32_t smb = (uint32_t)__cvta_generic_to_shared(smraw);
    const uint32_t* Q32 = (const uint32_t*)(smraw);
    uint32_t* P32 = (uint32_t*)(smraw + OFF_P);
    float* mrow = (float*)(smraw + OFF_ST);
    float* lrow = mrow + 64;
    float* arow = lrow + 64;

    const int b   = blockIdx.y;
    const int qt  = (int)gridDim.x - 1 - (int)blockIdx.x;  // long blocks first
    const int q0  = qt * 64;
    const int tid = threadIdx.x;
    const int lane = tid & 31, w = tid >> 5;    // w 0..15
    const int lq = lane >> 2, lr = lane & 3;
    const int wmQ = w >> 2, wnQ = w & 3;   // QK: 4m x 4n
    const int wmP = w >> 3, wnP = w & 7;   // PV: 2m x 8n
    const float scale = 0.088388347648318447f;  // 1/sqrt(128)

    // ---- prologue: G0 = {Q, K0, V0}; G1 = {K1, V1} if qt>=1 ----
    {
        const char* Qg = (const char*)(Q2h + ((size_t)b * NS + q0) * NDH);
#pragma unroll
        for (int f = tid; f < 1024; f += 512) {       // 64 rows x 16 chunks
            int row = f >> 4, c = f & 15;
            asm volatile("cp.async.cg.shared.global [%0], [%1], 16;\n"
                         :: "r"(smb + row * 272 + c * 16), "l"(Qg + (size_t)row * 256 + c * 16));
        }
        const char* Kg = (const char*)(K3h + ((size_t)b * NS) * NDH);
#pragma unroll
        for (int f = tid; f < 1024; f += 512) {
            int row = f >> 4, c = f & 15;
            asm volatile("cp.async.cg.shared.global [%0], [%1], 16;\n"
                         :: "r"(smb + OFF_K0 + row * 272 + c * 16), "l"(Kg + (size_t)row * 256 + c * 16));
        }
        const char* Vg = (const char*)(Vt + (size_t)b * NDV * NS);
#pragma unroll
        for (int f = tid; f < 4096; f += 512) {       // 512 rows x 8 chunks
            int n = f >> 3, c = f & 7;
            asm volatile("cp.async.cg.shared.global [%0], [%1], 16;\n"
                         :: "r"(smb + OFF_V0 + n * 144 + c * 16), "l"(Vg + (size_t)n * (NS*2) + c * 16));
        }
        asm volatile("cp.async.commit_group;\n" ::: "memory");
        if (qt >= 1) {
            const char* Kg1 = (const char*)(K3h + ((size_t)b * NS + 64) * NDH);
#pragma unroll
            for (int f = tid; f < 1024; f += 512) {
                int row = f >> 4, c = f & 15;
                asm volatile("cp.async.cg.shared.global [%0], [%1], 16;\n"
                             :: "r"(smb + OFF_K1 + row * 272 + c * 16), "l"(Kg1 + (size_t)row * 256 + c * 16));
            }
            const char* Vg1 = (const char*)(Vt + (size_t)b * NDV * NS) + 128;   // k0=64 -> 128B
#pragma unroll
            for (int f = tid; f < 4096; f += 512) {
                int n = f >> 3, c = f & 7;
                asm volatile("cp.async.cg.shared.global [%0], [%1], 16;\n"
                             :: "r"(smb + OFF_V1 + n * 144 + c * 16), "l"(Vg1 + (size_t)n * (NS*2) + c * 16));
            }
            asm volatile("cp.async.commit_group;\n" ::: "memory");
        }
    }
    if (tid < 64) { mrow[tid] = -1e30f; lrow[tid] = 0.f; }

    float oacc[2][8][4];
#pragma unroll
    for (int mt = 0; mt < 2; mt++)
#pragma unroll
        for (int nt = 0; nt < 8; nt++)
#pragma unroll
            for (int i = 0; i < 4; i++) oacc[mt][nt][i] = 0.f;

    for (int kt = 0; kt <= qt; kt++) {
        const int k0 = kt * 64;
        const uint32_t* K32 = (const uint32_t*)(smraw + ((kt & 1) ? OFF_K1 : OFF_K0));
        const uint32_t* V32 = (const uint32_t*)(smraw + ((kt & 1) ? OFF_V1 : OFF_V0));

        if (kt < qt) { asm volatile("cp.async.wait_group 1;\n" ::: "memory"); }
        else         { asm volatile("cp.async.wait_group 0;\n" ::: "memory"); }
        __syncthreads();

        // ---- S = Q @ K^T (warp: 16 rows x 16 cols), bf16 k16 ----
        float sacc[2][4];
#pragma unroll
        for (int nt = 0; nt < 2; nt++)
#pragma unroll
            for (int i = 0; i < 4; i++) sacc[nt][i] = 0.f;

        const int rq = (wmQ * 16 + lq) * 68;
#pragma unroll
        for (int ks = 0; ks < 8; ks++) {
            const int kw = ks * 8;
            uint32_t af[4];
            af[0] = Q32[rq            + kw + lr];
            af[1] = Q32[rq + 8*68     + kw + lr];
            af[2] = Q32[rq            + kw + 4 + lr];
            af[3] = Q32[rq + 8*68     + kw + 4 + lr];
#pragma unroll
            for (int nt = 0; nt < 2; nt++) {
                const int rk = (wnQ * 16 + nt * 8 + lq) * 68;
                mma16(sacc[nt], af, K32[rk + kw + lr], K32[rk + kw + 4 + lr]);
            }
        }
        // scale + mask + store bf16 scores into P
        {
            const bool diag = (kt == qt);
            const int rloc0 = wmQ * 16 + lq;
            const int grow0 = q0 + rloc0, grow1 = grow0 + 8;
#pragma unroll
            for (int nt = 0; nt < 2; nt++) {
                const int col = wnQ * 16 + nt * 8 + lr * 2;
                const int gc0 = k0 + col, gc1 = gc0 + 1;
                float v0 = sacc[nt][0] * scale;
                float v1 = sacc[nt][1] * scale;
                float v2 = sacc[nt][2] * scale;
                float v3 = sacc[nt][3] * scale;
                if (diag) {
                    if (gc0 > grow0) v0 = -1e30f;
                    if (gc1 > grow0) v1 = -1e30f;
                    if (gc0 > grow1) v2 = -1e30f;
                    if (gc1 > grow1) v3 = -1e30f;
                }
                P32[rloc0 * 36 + (col >> 1)]       = bfpack(v0, v1);
                P32[(rloc0 + 8) * 36 + (col >> 1)] = bfpack(v2, v3);
            }
        }
        __syncthreads();

        // ---- online softmax (8 threads/row, 8 cols each), in-place bf16 RMW ----
        {
            const int row = tid >> 3, g = tid & 7;
            const int base = row * 36 + g * 4;
            uint32_t wd[4];
            float f[8];
#pragma unroll
            for (int i = 0; i < 4; i++) {
                wd[i] = P32[base + i];
                f[2*i]   = bflo(wd[i]);
                f[2*i+1] = bfhi(wd[i]);
            }
            float mx = -1e30f;
#pragma unroll
            for (int c = 0; c < 8; c++) mx = fmaxf(mx, f[c]);
            mx = fmaxf(mx, __shfl_xor_sync(0xffffffffu, mx, 1));
            mx = fmaxf(mx, __shfl_xor_sync(0xffffffffu, mx, 2));
            mx = fmaxf(mx, __shfl_xor_sync(0xffffffffu, mx, 4));
            const float mold = mrow[row];
            const float mnew = fmaxf(mold, mx);
            const float al   = __expf(mold - mnew);
            float sum = 0.f;
#pragma unroll
            for (int c = 0; c < 8; c++) {
                f[c] = __expf(f[c] - mnew);
                sum += f[c];
            }
#pragma unroll
            for (int i = 0; i < 4; i++) P32[base + i] = bfpack(f[2*i], f[2*i+1]);
            sum += __shfl_xor_sync(0xffffffffu, sum, 1);
            sum += __shfl_xor_sync(0xffffffffu, sum, 2);
            sum += __shfl_xor_sync(0xffffffffu, sum, 4);
            if (g == 0) {
                mrow[row] = mnew;
                lrow[row] = lrow[row] * al + sum;
                arow[row] = al;
            }
        }
        __syncthreads();

        // ---- rescale O, then O += P @ V (bf16 k16; warp 32 rows x 64 cols) ----
        {
            const int rb = wmP * 32;
            const float al00 = arow[rb + lq];
            const float al01 = arow[rb + lq + 8];
            const float al10 = arow[rb + 16 + lq];
            const float al11 = arow[rb + 16 + lq + 8];
#pragma unroll
            for (int nt = 0; nt < 8; nt++) {
                oacc[0][nt][0] *= al00; oacc[0][nt][1] *= al00;
                oacc[0][nt][2] *= al01; oacc[0][nt][3] *= al01;
                oacc[1][nt][0] *= al10; oacc[1][nt][1] *= al10;
                oacc[1][nt][2] *= al11; oacc[1][nt][3] *= al11;
            }
#pragma unroll
            for (int ks = 0; ks < 4; ks++) {
                const int kw = ks * 8;
                uint32_t af[2][4];
#pragma unroll
                for (int mt = 0; mt < 2; mt++) {
                    const int rp = (rb + mt * 16 + lq) * 36;
                    af[mt][0] = P32[rp          + kw + lr];
                    af[mt][1] = P32[rp + 8*36   + kw + lr];
                    af[mt][2] = P32[rp          + kw + 4 + lr];
                    af[mt][3] = P32[rp + 8*36   + kw + 4 + lr];
                }
#pragma unroll
                for (int nt = 0; nt < 8; nt++) {
                    const int cb = (wnP * 64 + nt * 8 + lq) * 36;
                    uint32_t b0 = V32[cb + kw + lr];
                    uint32_t b1 = V32[cb + kw + 4 + lr];
                    mma16(oacc[0][nt], af[0], b0, b1);
                    mma16(oacc[1][nt], af[1], b0, b1);
                }
            }
        }
        __syncthreads();   // PV done reading V/P buffers

        // ---- issue G(kt+2) into buf[kt&1] ----
        if (kt + 2 <= qt) {
            const int kn = k0 + 128;
            const uint32_t koff = (kt & 1) ? OFF_K1 : OFF_K0;
            const uint32_t voff = (kt & 1) ? OFF_V1 : OFF_V0;
            const char* Kg = (const char*)(K3h + ((size_t)b * NS + kn) * NDH);
#pragma unroll
            for (int f = tid; f < 1024; f += 512) {
                int row = f >> 4, c = f & 15;
                asm volatile("cp.async.cg.shared.global [%0], [%1], 16;\n"
                             :: "r"(smb + koff + row * 272 + c * 16), "l"(Kg + (size_t)row * 256 + c * 16));
            }
            const char* Vg = (const char*)(Vt + (size_t)b * NDV * NS) + (size_t)kn * 2;
#pragma unroll
            for (int f = tid; f < 4096; f += 512) {
                int n = f >> 3, c = f & 7;
                asm volatile("cp.async.cg.shared.global [%0], [%1], 16;\n"
                             :: "r"(smb + voff + n * 144 + c * 16), "l"(Vg + (size_t)n * (NS*2) + c * 16));
            }
            asm volatile("cp.async.commit_group;\n" ::: "memory");
        }
    }

    __syncthreads();
    // epilogue: normalize and store fp32
    {
        const int rb = wmP * 32;
        float li[2][2];
        li[0][0] = 1.f / lrow[rb + lq];
        li[0][1] = 1.f / lrow[rb + lq + 8];
        li[1][0] = 1.f / lrow[rb + 16 + lq];
        li[1][1] = 1.f / lrow[rb + 16 + lq + 8];
#pragma unroll
        for (int mt = 0; mt < 2; mt++) {
            const int gr = q0 + rb + mt * 16 + lq;
#pragma unroll
            for (int nt = 0; nt < 8; nt++) {
                const int col = wnP * 64 + nt * 8 + lr * 2;
                *(float2*)(O + ((size_t)b * NS + gr) * NDV + col) =
                    make_float2(oacc[mt][nt][0] * li[mt][0], oacc[mt][nt][1] * li[mt][0]);
                *(float2*)(O + ((size_t)b * NS + gr + 8) * NDV + col) =
                    make_float2(oacc[mt][nt][2] * li[mt][1], oacc[mt][nt][3] * li[mt][1]);
            }
        }
    }
}

// ---------------------------------------------------------------------------
extern "C" void kernel_launch(void* const* d_in, const int* in_sizes, int n_in,
                              void* d_out, int out_size)
{
    const float* q  = (const float*)d_in[0];
    const float* k  = (const float*)d_in[1];
    const float* v  = (const float*)d_in[2];
    const float* w1 = (const float*)d_in[3];
    const float* w2 = (const float*)d_in[4];
    const float* w3 = (const float*)d_in[5];
    const float* w4 = (const float*)d_in[6];
    const float* w6 = (const float*)d_in[7];
    const float* w7 = (const float*)d_in[8];
    float* out = (float*)d_out;

    static float *W12 = nullptr, *W46, *Q3, *ATTN;
    static __nv_bfloat16 *Q2h, *K3h, *Vt;
    static bool init_done = false;
    if (!init_done) {
        cudaGetSymbolAddress((void**)&W12,  g_W12);
        cudaGetSymbolAddress((void**)&W46,  g_W46);
        cudaGetSymbolAddress((void**)&Q2h,  g_Q2h);
        cudaGetSymbolAddress((void**)&K3h,  g_K3h);
        cudaGetSymbolAddress((void**)&Vt,   g_Vt);
        cudaGetSymbolAddress((void**)&Q3,   g_Q3);
        cudaGetSymbolAddress((void**)&ATTN, g_ATTN);
        cudaFuncSetAttribute(flash_attn_bf16, cudaFuncAttributeMaxDynamicSharedMemorySize, SMEM_ATTN);
        init_done = true;
    }

    // 1) weight prep + V transpose (independent)
    weight_prep_kernel<<<dim3(ND/128, 2), 256>>>(w1, w2, W12, w4, w6, W46);
    vt_kernel<<<dim3(NS/32, NDV/32, NB), 256>>>(v, Vt);

    // 2) projections: Q2h = bf16(q@W12), K3h = bf16(k@W46), Q3 = q@w3
    proj_kernel<<<dim3(NM/128, 6), 256>>>(q, k, W12, W46, w3, Q2h, K3h, Q3);

    // 3) causal flash attention (bf16 tensor cores, 2-deep cp.async pipeline)
    flash_attn_bf16<<<dim3(NS/64, NB), 512, SMEM_ATTN>>>(Q2h, K3h, Vt, ATTN);

    // 4) final: out = (ATTN + Q3) @ (w7_top + w7_bot)
    final_kernel<<<dim3(NM/128, NDOUT/128), 256>>>(ATTN, Q3, w7, out);
}

// round 8
// speedup vs baseline: 2.2391x; 1.1550x over previous
#include <cuda_runtime.h>
#include <cuda_bf16.h>
#include <math.h>
#include <stdint.h>

#define NB 8
#define NS 2048
#define ND 1024
#define NH1 512
#define NDH 128
#define NDV 512
#define NDOUT 512
#define NM (NB*NS)   // 16384

// scratch (device globals: allocation-free per harness rules)
__device__ float g_W12[ND*NDH];
__device__ float g_W46[ND*NDH];
__device__ float g_WSUM[NDV*NDOUT];
__device__ float g_w3r[ND*NDV];
__device__ __nv_bfloat16 g_Q2h[(size_t)NM*NDH];
__device__ __nv_bfloat16 g_K3h[(size_t)NM*NDH];
__device__ __nv_bfloat16 g_Vt[(size_t)NB*NDV*NS];   // [b][dv][seq]
__device__ float g_Q3[(size_t)NM*NDV];
__device__ float g_ATTN[(size_t)NM*NDV];            // holds attn_out + q3

// ---------------------------------------------------------------------------
// helpers
// ---------------------------------------------------------------------------
__device__ __forceinline__ float to_tf32(float x) {
    float r;
    asm("cvt.rna.tf32.f32 %0, %1;" : "=f"(r) : "f"(x));
    return r;
}
__device__ __forceinline__ uint32_t fbits(float x) { return __float_as_uint(x); }
__device__ __forceinline__ uint32_t bfpack(float lo, float hi) {
    uint32_t r;
    asm("cvt.rn.bf16x2.f32 %0, %1, %2;" : "=r"(r) : "f"(hi), "f"(lo));
    return r;
}
__device__ __forceinline__ float bflo(uint32_t w) { return __uint_as_float(w << 16); }
__device__ __forceinline__ float bfhi(uint32_t w) { return __uint_as_float(w & 0xffff0000u); }

// D += A@B  (m16n8k8, tf32, row.col)
__device__ __forceinline__ void mma8(float d[4], const uint32_t a[4],
                                     uint32_t b0, uint32_t b1) {
    asm volatile(
        "mma.sync.aligned.m16n8k8.row.col.f32.tf32.tf32.f32 "
        "{%0,%1,%2,%3},{%4,%5,%6,%7},{%8,%9},{%0,%1,%2,%3};"
        : "+f"(d[0]), "+f"(d[1]), "+f"(d[2]), "+f"(d[3])
        : "r"(a[0]), "r"(a[1]), "r"(a[2]), "r"(a[3]), "r"(b0), "r"(b1));
}
// D += A@B  (m16n8k16, bf16, row.col)
__device__ __forceinline__ void mma16(float d[4], const uint32_t a[4],
                                      uint32_t b0, uint32_t b1) {
    asm volatile(
        "mma.sync.aligned.m16n8k16.row.col.f32.bf16.bf16.f32 "
        "{%0,%1,%2,%3},{%4,%5,%6,%7},{%8,%9},{%0,%1,%2,%3};"
        : "+f"(d[0]), "+f"(d[1]), "+f"(d[2]), "+f"(d[3])
        : "r"(a[0]), "r"(a[1]), "r"(a[2]), "r"(a[3]), "r"(b0), "r"(b1));
}

// ---------------------------------------------------------------------------
// Async TF32 GEMM: C[128x128 tile] = A @ B, 4-stage cp.async pipeline, BK=16.
// A staged row-major pitch 20 words (lq*20+lr hits 32 distinct banks);
// B staged k-major pitch 136 (lr*8+lq distinct). A is raw fp32 (tf32-truncated
// by the mma); B must be pre-rounded tf32 for full accuracy.
// 256 threads = 8 warps (2m x 4n), warp tile 64x32.
// ---------------------------------------------------------------------------
#define GSTG 18944          // stage bytes: A 128*20*4=10240 + B 16*136*4=8704
#define GSMEM (4*GSTG)      // 75776

__device__ __forceinline__ void g_issue(uint32_t smb, const float* Ab, const float* Bb,
                                        int K, int N, int s, int nk, int tid)
{
    if (s < nk) {
        const uint32_t sb = smb + (uint32_t)(s & 3) * GSTG;
        const char* Ag = (const char*)(Ab + (size_t)s * 16);
#pragma unroll
        for (int f = tid; f < 512; f += 256) {
            int row = f >> 2, c = f & 3;
            asm volatile("cp.async.cg.shared.global [%0], [%1], 16;\n"
                         :: "r"(sb + row * 80 + c * 16),
                            "l"(Ag + ((size_t)row * K + c * 4) * 4));
        }
        const char* Bg = (const char*)(Bb + (size_t)s * 16 * N);
#pragma unroll
        for (int f = tid; f < 512; f += 256) {
            int row = f >> 5, c = f & 31;
            asm volatile("cp.async.cg.shared.global [%0], [%1], 16;\n"
                         :: "r"(sb + 10240 + row * 544 + c * 16),
                            "l"(Bg + ((size_t)row * N + c * 4) * 4));
        }
    }
    asm volatile("cp.async.commit_group;\n" ::: "memory");  // empty group if s>=nk
}

template<bool BF16OUT, bool TF32OUT>
__device__ __forceinline__ void gemm_async_body(
    char* smraw, const float* __restrict__ A, const float* __restrict__ B,
    void* __restrict__ Cv, int N, int K, int brow, int bcol)
{
    const uint32_t smb = (uint32_t)__cvta_generic_to_shared(smraw);
    const int tid = threadIdx.x, lane = tid & 31, w = tid >> 5;
    const int lq = lane >> 2, lr = lane & 3;
    const int wm = w >> 2, wn = w & 3;
    const float* Ab = A + (size_t)brow * K;
    const float* Bb = B + bcol;
    const int nk = K / 16;

    float acc[4][4][4];
#pragma unroll
    for (int mt = 0; mt < 4; mt++)
#pragma unroll
        for (int nt = 0; nt < 4; nt++)
#pragma unroll
            for (int i = 0; i < 4; i++) acc[mt][nt][i] = 0.f;

    g_issue(smb, Ab, Bb, K, N, 0, nk, tid);
    g_issue(smb, Ab, Bb, K, N, 1, nk, tid);
    g_issue(smb, Ab, Bb, K, N, 2, nk, tid);

    for (int kt = 0; kt < nk; kt++) {
        asm volatile("cp.async.wait_group 2;\n" ::: "memory");
        __syncthreads();                     // stage kt visible; stage kt-1 consumers done
        g_issue(smb, Ab, Bb, K, N, kt + 3, nk, tid);   // overwrites buf (kt-1)&3

        const float* As = (const float*)(smraw + (kt & 3) * GSTG);
        const float* Bs = (const float*)(smraw + (kt & 3) * GSTG + 10240);
#pragma unroll
        for (int ks = 0; ks < 2; ks++) {
            const int kw = ks * 8;
            uint32_t af[4][4], bf[4][2];
#pragma unroll
            for (int mt = 0; mt < 4; mt++) {
                const int bm = wm * 64 + mt * 16;
                af[mt][0] = fbits(As[(bm + lq    ) * 20 + kw + lr]);
                af[mt][1] = fbits(As[(bm + lq + 8) * 20 + kw + lr]);
                af[mt][2] = fbits(As[(bm + lq    ) * 20 + kw + 4 + lr]);
                af[mt][3] = fbits(As[(bm + lq + 8) * 20 + kw + 4 + lr]);
            }
#pragma unroll
            for (int nt = 0; nt < 4; nt++) {
                const int bn = wn * 32 + nt * 8;
                bf[nt][0] = fbits(Bs[(kw + lr    ) * 136 + bn + lq]);
                bf[nt][1] = fbits(Bs[(kw + 4 + lr) * 136 + bn + lq]);
            }
#pragma unroll
            for (int mt = 0; mt < 4; mt++)
#pragma unroll
                for (int nt = 0; nt < 4; nt++)
                    mma8(acc[mt][nt], af[mt], bf[nt][0], bf[nt][1]);
        }
    }

    // epilogue
#pragma unroll
    for (int mt = 0; mt < 4; mt++) {
        const int r0 = brow + wm * 64 + mt * 16 + lq;
#pragma unroll
        for (int nt = 0; nt < 4; nt++) {
            const int col = bcol + wn * 32 + nt * 8 + lr * 2;
            if (BF16OUT) {
                uint32_t* C = (uint32_t*)Cv;
                C[((size_t)r0 * N + col) >> 1]       = bfpack(acc[mt][nt][0], acc[mt][nt][1]);
                C[((size_t)(r0 + 8) * N + col) >> 1] = bfpack(acc[mt][nt][2], acc[mt][nt][3]);
            } else {
                float* C = (float*)Cv;
                float o0 = acc[mt][nt][0], o1 = acc[mt][nt][1];
                float o2 = acc[mt][nt][2], o3 = acc[mt][nt][3];
                if (TF32OUT) { o0 = to_tf32(o0); o1 = to_tf32(o1); o2 = to_tf32(o2); o3 = to_tf32(o3); }
                *(float2*)(C + (size_t)r0 * N + col)       = make_float2(o0, o1);
                *(float2*)(C + (size_t)(r0 + 8) * N + col) = make_float2(o2, o3);
            }
        }
    }
}

// ---- GEMM wrapper launches ----
// weight prep: W12 = tf32(w1@w2) (y=0), W46 = tf32(w4@w6) (y=1). grid(8,2)
__global__ __launch_bounds__(256, 2) void weight_prep_kernel(
    const float* __restrict__ w1, const float* __restrict__ w2, float* __restrict__ W12,
    const float* __restrict__ w4, const float* __restrict__ w6, float* __restrict__ W46)
{
    extern __shared__ char sm[];
    if (blockIdx.y == 0)
        gemm_async_body<false,true>(sm, w1, w2, W12, NDH, NH1, blockIdx.x*128, 0);
    else
        gemm_async_body<false,true>(sm, w4, w6, W46, NDH, NH1, blockIdx.x*128, 0);
}

// misc prep: w3r = tf32(w3); WSUM = tf32(w7_top + w7_bot)
__global__ __launch_bounds__(256) void misc_prep(
    const float* __restrict__ w3, const float* __restrict__ w7,
    float* __restrict__ w3r, float* __restrict__ wsum)
{
    int i = blockIdx.x * 256 + threadIdx.x;
    if (i < ND*NDV) w3r[i] = to_tf32(w3[i]);
    if (i < NDV*NDOUT) wsum[i] = to_tf32(w7[i] + w7[i + (size_t)NDV*NDOUT]);
}

// V transpose + bf16: Vt[b][n][s] = bf16(V[b][s][n])
__global__ __launch_bounds__(256) void vt_kernel(const float* __restrict__ V,
                                                 __nv_bfloat16* __restrict__ Vt)
{
    __shared__ float t[32][33];
    const int s0 = blockIdx.x * 32, n0 = blockIdx.y * 32, b = blockIdx.z;
    const int tx = threadIdx.x & 31, ty = threadIdx.x >> 5;   // 32 x 8
#pragma unroll
    for (int j = 0; j < 4; j++) {
        int s = s0 + ty + j * 8;
        t[ty + j * 8][tx] = V[((size_t)b * NS + s) * NDV + n0 + tx];
    }
    __syncthreads();
#pragma unroll
    for (int j = 0; j < 4; j++) {
        int n = n0 + ty + j * 8;
        Vt[((size_t)b * NDV + n) * NS + s0 + tx] = __float2bfloat16_rn(t[tx][ty + j * 8]);
    }
}

// projections: y=0 -> Q2h (bf16); y=1 -> K3h (bf16); y=2..5 -> Q3 (fp32). grid(128,6)
__global__ __launch_bounds__(256, 2) void proj_kernel(
    const float* __restrict__ q, const float* __restrict__ k,
    const float* __restrict__ W12, const float* __restrict__ W46,
    const float* __restrict__ w3r,
    __nv_bfloat16* __restrict__ Q2h, __nv_bfloat16* __restrict__ K3h,
    float* __restrict__ Q3)
{
    extern __shared__ char sm[];
    const int y = blockIdx.y;
    if (y == 0)
        gemm_async_body<true,false>(sm, q, W12, Q2h, NDH, ND, blockIdx.x*128, 0);
    else if (y == 1)
        gemm_async_body<true,false>(sm, k, W46, K3h, NDH, ND, blockIdx.x*128, 0);
    else
        gemm_async_body<false,false>(sm, q, w3r, Q3, NDV, ND, blockIdx.x*128, (y-2)*128);
}

// final: out = ATTNQ3 @ WSUM. grid(128,4)
__global__ __launch_bounds__(256, 2) void final_kernel(
    const float* __restrict__ ATTNQ3, const float* __restrict__ WSUM,
    float* __restrict__ out)
{
    extern __shared__ char sm[];
    gemm_async_body<false,false>(sm, ATTNQ3, WSUM, out, NDOUT, NDV,
                                 blockIdx.x*128, blockIdx.y*128);
}

// ---------------------------------------------------------------------------
// Flash attention (causal), bf16 mma (m16n8k16). BM=BN=64, DH=128, DV=512.
// 512 threads. K,V double-buffered; 2-deep cp.async group pipeline.
// Epilogue fuses + Q3 (output buffer holds attn_out + q3).
// ---------------------------------------------------------------------------
#define OFF_K0 17408
#define OFF_K1 34816
#define OFF_P  52224
#define OFF_V0 61440
#define OFF_V1 135168
#define OFF_ST 208896
#define SMEM_ATTN 209664

__global__ __launch_bounds__(512) void flash_attn_bf16(
    const __nv_bfloat16* __restrict__ Q2h, const __nv_bfloat16* __restrict__ K3h,
    const __nv_bfloat16* __restrict__ Vt, const float* __restrict__ Q3,
    float* __restrict__ O)
{
    extern __shared__ char smraw[];
    const uint32_t smb = (uint32_t)__cvta_generic_to_shared(smraw);
    const uint32_t* Q32 = (const uint32_t*)(smraw);
    uint32_t* P32 = (uint32_t*)(smraw + OFF_P);
    float* mrow = (float*)(smraw + OFF_ST);
    float* lrow = mrow + 64;
    float* arow = lrow + 64;

    const int b   = blockIdx.y;
    const int qt  = (int)gridDim.x - 1 - (int)blockIdx.x;  // long blocks first
    const int q0  = qt * 64;
    const int tid = threadIdx.x;
    const int lane = tid & 31, w = tid >> 5;    // w 0..15
    const int lq = lane >> 2, lr = lane & 3;
    const int wmQ = w >> 2, wnQ = w & 3;   // QK: 4m x 4n
    const int wmP = w >> 3, wnP = w & 7;   // PV: 2m x 8n
    const float scale = 0.088388347648318447f;  // 1/sqrt(128)

    // ---- prologue: G0 = {Q, K0, V0}; G1 = {K1, V1} if qt>=1 ----
    {
        const char* Qg = (const char*)(Q2h + ((size_t)b * NS + q0) * NDH);
#pragma unroll
        for (int f = tid; f < 1024; f += 512) {
            int row = f >> 4, c = f & 15;
            asm volatile("cp.async.cg.shared.global [%0], [%1], 16;\n"
                         :: "r"(smb + row * 272 + c * 16), "l"(Qg + (size_t)row * 256 + c * 16));
        }
        const char* Kg = (const char*)(K3h + ((size_t)b * NS) * NDH);
#pragma unroll
        for (int f = tid; f < 1024; f += 512) {
            int row = f >> 4, c = f & 15;
            asm volatile("cp.async.cg.shared.global [%0], [%1], 16;\n"
                         :: "r"(smb + OFF_K0 + row * 272 + c * 16), "l"(Kg + (size_t)row * 256 + c * 16));
        }
        const char* Vg = (const char*)(Vt + (size_t)b * NDV * NS);
#pragma unroll
        for (int f = tid; f < 4096; f += 512) {
            int n = f >> 3, c = f & 7;
            asm volatile("cp.async.cg.shared.global [%0], [%1], 16;\n"
                         :: "r"(smb + OFF_V0 + n * 144 + c * 16), "l"(Vg + (size_t)n * (NS*2) + c * 16));
        }
        asm volatile("cp.async.commit_group;\n" ::: "memory");
        if (qt >= 1) {
            const char* Kg1 = (const char*)(K3h + ((size_t)b * NS + 64) * NDH);
#pragma unroll
            for (int f = tid; f < 1024; f += 512) {
                int row = f >> 4, c = f & 15;
                asm volatile("cp.async.cg.shared.global [%0], [%1], 16;\n"
                             :: "r"(smb + OFF_K1 + row * 272 + c * 16), "l"(Kg1 + (size_t)row * 256 + c * 16));
            }
            const char* Vg1 = (const char*)(Vt + (size_t)b * NDV * NS) + 128;
#pragma unroll
            for (int f = tid; f < 4096; f += 512) {
                int n = f >> 3, c = f & 7;
                asm volatile("cp.async.cg.shared.global [%0], [%1], 16;\n"
                             :: "r"(smb + OFF_V1 + n * 144 + c * 16), "l"(Vg1 + (size_t)n * (NS*2) + c * 16));
            }
            asm volatile("cp.async.commit_group;\n" ::: "memory");
        }
    }
    if (tid < 64) { mrow[tid] = -1e30f; lrow[tid] = 0.f; }

    float oacc[2][8][4];
#pragma unroll
    for (int mt = 0; mt < 2; mt++)
#pragma unroll
        for (int nt = 0; nt < 8; nt++)
#pragma unroll
            for (int i = 0; i < 4; i++) oacc[mt][nt][i] = 0.f;

    for (int kt = 0; kt <= qt; kt++) {
        const int k0 = kt * 64;
        const uint32_t* K32 = (const uint32_t*)(smraw + ((kt & 1) ? OFF_K1 : OFF_K0));
        const uint32_t* V32 = (const uint32_t*)(smraw + ((kt & 1) ? OFF_V1 : OFF_V0));

        if (kt < qt) { asm volatile("cp.async.wait_group 1;\n" ::: "memory"); }
        else         { asm volatile("cp.async.wait_group 0;\n" ::: "memory"); }
        __syncthreads();

        // ---- S = Q @ K^T (warp: 16 rows x 16 cols), bf16 k16 ----
        float sacc[2][4];
#pragma unroll
        for (int nt = 0; nt < 2; nt++)
#pragma unroll
            for (int i = 0; i < 4; i++) sacc[nt][i] = 0.f;

        const int rq = (wmQ * 16 + lq) * 68;
#pragma unroll
        for (int ks = 0; ks < 8; ks++) {
            const int kw = ks * 8;
            uint32_t af[4];
            af[0] = Q32[rq        + kw + lr];
            af[1] = Q32[rq + 8*68 + kw + lr];
            af[2] = Q32[rq        + kw + 4 + lr];
            af[3] = Q32[rq + 8*68 + kw + 4 + lr];
#pragma unroll
            for (int nt = 0; nt < 2; nt++) {
                const int rk = (wnQ * 16 + nt * 8 + lq) * 68;
                mma16(sacc[nt], af, K32[rk + kw + lr], K32[rk + kw + 4 + lr]);
            }
        }
        // scale + mask + store bf16 scores into P
        {
            const bool diag = (kt == qt);
            const int rloc0 = wmQ * 16 + lq;
            const int grow0 = q0 + rloc0, grow1 = grow0 + 8;
#pragma unroll
            for (int nt = 0; nt < 2; nt++) {
                const int col = wnQ * 16 + nt * 8 + lr * 2;
                const int gc0 = k0 + col, gc1 = gc0 + 1;
                float v0 = sacc[nt][0] * scale;
                float v1 = sacc[nt][1] * scale;
                float v2 = sacc[nt][2] * scale;
                float v3 = sacc[nt][3] * scale;
                if (diag) {
                    if (gc0 > grow0) v0 = -1e30f;
                    if (gc1 > grow0) v1 = -1e30f;
                    if (gc0 > grow1) v2 = -1e30f;
                    if (gc1 > grow1) v3 = -1e30f;
                }
                P32[rloc0 * 36 + (col >> 1)]       = bfpack(v0, v1);
                P32[(rloc0 + 8) * 36 + (col >> 1)] = bfpack(v2, v3);
            }
        }
        __syncthreads();

        // ---- online softmax (8 threads/row, 8 cols each), in-place bf16 RMW ----
        {
            const int row = tid >> 3, g = tid & 7;
            const int base = row * 36 + g * 4;
            uint32_t wd[4];
            float f[8];
#pragma unroll
            for (int i = 0; i < 4; i++) {
                wd[i] = P32[base + i];
                f[2*i]   = bflo(wd[i]);
                f[2*i+1] = bfhi(wd[i]);
            }
            float mx = -1e30f;
#pragma unroll
            for (int c = 0; c < 8; c++) mx = fmaxf(mx, f[c]);
            mx = fmaxf(mx, __shfl_xor_sync(0xffffffffu, mx, 1));
            mx = fmaxf(mx, __shfl_xor_sync(0xffffffffu, mx, 2));
            mx = fmaxf(mx, __shfl_xor_sync(0xffffffffu, mx, 4));
            const float mold = mrow[row];
            const float mnew = fmaxf(mold, mx);
            const float al   = __expf(mold - mnew);
            float sum = 0.f;
#pragma unroll
            for (int c = 0; c < 8; c++) {
                f[c] = __expf(f[c] - mnew);
                sum += f[c];
            }
#pragma unroll
            for (int i = 0; i < 4; i++) P32[base + i] = bfpack(f[2*i], f[2*i+1]);
            sum += __shfl_xor_sync(0xffffffffu, sum, 1);
            sum += __shfl_xor_sync(0xffffffffu, sum, 2);
            sum += __shfl_xor_sync(0xffffffffu, sum, 4);
            if (g == 0) {
                mrow[row] = mnew;
                lrow[row] = lrow[row] * al + sum;
                arow[row] = al;
            }
        }
        __syncthreads();

        // ---- rescale O, then O += P @ V (bf16 k16; warp 32 rows x 64 cols) ----
        {
            const int rb = wmP * 32;
            const float al00 = arow[rb + lq];
            const float al01 = arow[rb + lq + 8];
            const float al10 = arow[rb + 16 + lq];
            const float al11 = arow[rb + 16 + lq + 8];
#pragma unroll
            for (int nt = 0; nt < 8; nt++) {
                oacc[0][nt][0] *= al00; oacc[0][nt][1] *= al00;
                oacc[0][nt][2] *= al01; oacc[0][nt][3] *= al01;
                oacc[1][nt][0] *= al10; oacc[1][nt][1] *= al10;
                oacc[1][nt][2] *= al11; oacc[1][nt][3] *= al11;
            }
#pragma unroll
            for (int ks = 0; ks < 4; ks++) {
                const int kw = ks * 8;
                uint32_t af[2][4];
#pragma unroll
                for (int mt = 0; mt < 2; mt++) {
                    const int rp = (rb + mt * 16 + lq) * 36;
                    af[mt][0] = P32[rp        + kw + lr];
                    af[mt][1] = P32[rp + 8*36 + kw + lr];
                    af[mt][2] = P32[rp        + kw + 4 + lr];
                    af[mt][3] = P32[rp + 8*36 + kw + 4 + lr];
                }
#pragma unroll
                for (int nt = 0; nt < 8; nt++) {
                    const int cb = (wnP * 64 + nt * 8 + lq) * 36;
                    uint32_t b0 = V32[cb + kw + lr];
                    uint32_t b1 = V32[cb + kw + 4 + lr];
                    mma16(oacc[0][nt], af[0], b0, b1);
                    mma16(oacc[1][nt], af[1], b0, b1);
                }
            }
        }
        __syncthreads();   // PV done reading V/P buffers

        // ---- issue G(kt+2) into buf[kt&1] ----
        if (kt + 2 <= qt) {
            const int kn = k0 + 128;
            const uint32_t koff = (kt & 1) ? OFF_K1 : OFF_K0;
            const uint32_t voff = (kt & 1) ? OFF_V1 : OFF_V0;
            const char* Kg = (const char*)(K3h + ((size_t)b * NS + kn) * NDH);
#pragma unroll
            for (int f = tid; f < 1024; f += 512) {
                int row = f >> 4, c = f & 15;
                asm volatile("cp.async.cg.shared.global [%0], [%1], 16;\n"
                             :: "r"(smb + koff + row * 272 + c * 16), "l"(Kg + (size_t)row * 256 + c * 16));
            }
            const char* Vg = (const char*)(Vt + (size_t)b * NDV * NS) + (size_t)kn * 2;
#pragma unroll
            for (int f = tid; f < 4096; f += 512) {
                int n = f >> 3, c = f & 7;
                asm volatile("cp.async.cg.shared.global [%0], [%1], 16;\n"
                             :: "r"(smb + voff + n * 144 + c * 16), "l"(Vg + (size_t)n * (NS*2) + c * 16));
            }
            asm volatile("cp.async.commit_group;\n" ::: "memory");
        }
    }

    __syncthreads();
    // epilogue: normalize, add Q3, store fp32 (O holds attn_out + q3)
    {
        const int rb = wmP * 32;
        float li[2][2];
        li[0][0] = 1.f / lrow[rb + lq];
        li[0][1] = 1.f / lrow[rb + lq + 8];
        li[1][0] = 1.f / lrow[rb + 16 + lq];
        li[1][1] = 1.f / lrow[rb + 16 + lq + 8];
#pragma unroll
        for (int mt = 0; mt < 2; mt++) {
            const int gr = q0 + rb + mt * 16 + lq;
#pragma unroll
            for (int nt = 0; nt < 8; nt++) {
                const int col = wnP * 64 + nt * 8 + lr * 2;
                const size_t i0 = ((size_t)b * NS + gr) * NDV + col;
                const size_t i1 = ((size_t)b * NS + gr + 8) * NDV + col;
                float2 q30 = *(const float2*)(Q3 + i0);
                float2 q31 = *(const float2*)(Q3 + i1);
                *(float2*)(O + i0) = make_float2(oacc[mt][nt][0] * li[mt][0] + q30.x,
                                                 oacc[mt][nt][1] * li[mt][0] + q30.y);
                *(float2*)(O + i1) = make_float2(oacc[mt][nt][2] * li[mt][1] + q31.x,
                                                 oacc[mt][nt][3] * li[mt][1] + q31.y);
            }
        }
    }
}

// ---------------------------------------------------------------------------
extern "C" void kernel_launch(void* const* d_in, const int* in_sizes, int n_in,
                              void* d_out, int out_size)
{
    const float* q  = (const float*)d_in[0];
    const float* k  = (const float*)d_in[1];
    const float* v  = (const float*)d_in[2];
    const float* w1 = (const float*)d_in[3];
    const float* w2 = (const float*)d_in[4];
    const float* w3 = (const float*)d_in[5];
    const float* w4 = (const float*)d_in[6];
    const float* w6 = (const float*)d_in[7];
    const float* w7 = (const float*)d_in[8];
    float* out = (float*)d_out;

    static float *W12 = nullptr, *W46, *WSUM, *w3r, *Q3, *ATTN;
    static __nv_bfloat16 *Q2h, *K3h, *Vt;
    static bool init_done = false;
    if (!init_done) {
        cudaGetSymbolAddress((void**)&W12,  g_W12);
        cudaGetSymbolAddress((void**)&W46,  g_W46);
        cudaGetSymbolAddress((void**)&WSUM, g_WSUM);
        cudaGetSymbolAddress((void**)&w3r,  g_w3r);
        cudaGetSymbolAddress((void**)&Q2h,  g_Q2h);
        cudaGetSymbolAddress((void**)&K3h,  g_K3h);
        cudaGetSymbolAddress((void**)&Vt,   g_Vt);
        cudaGetSymbolAddress((void**)&Q3,   g_Q3);
        cudaGetSymbolAddress((void**)&ATTN, g_ATTN);
        cudaFuncSetAttribute(flash_attn_bf16,   cudaFuncAttributeMaxDynamicSharedMemorySize, SMEM_ATTN);
        cudaFuncSetAttribute(weight_prep_kernel, cudaFuncAttributeMaxDynamicSharedMemorySize, GSMEM);
        cudaFuncSetAttribute(proj_kernel,        cudaFuncAttributeMaxDynamicSharedMemorySize, GSMEM);
        cudaFuncSetAttribute(final_kernel,       cudaFuncAttributeMaxDynamicSharedMemorySize, GSMEM);
        init_done = true;
    }

    // 1) prep: W12/W46 GEMMs, WSUM + w3 rounding, V transpose
    weight_prep_kernel<<<dim3(ND/128, 2), 256, GSMEM>>>(w1, w2, W12, w4, w6, W46);
    misc_prep<<<(ND*NDV + 255)/256, 256>>>(w3, w7, w3r, WSUM);
    vt_kernel<<<dim3(NS/32, NDV/32, NB), 256>>>(v, Vt);

    // 2) projections: Q2h = bf16(q@W12), K3h = bf16(k@W46), Q3 = q@w3r
    proj_kernel<<<dim3(NM/128, 6), 256, GSMEM>>>(q, k, W12, W46, w3r, Q2h, K3h, Q3);

    // 3) causal flash attention; epilogue writes attn_out + q3
    flash_attn_bf16<<<dim3(NS/64, NB), 512, SMEM_ATTN>>>(Q2h, K3h, Vt, Q3, ATTN);

    // 4) final: out = (attn_out + q3) @ WSUM
    final_kernel<<<dim3(NM/128, NDOUT/128), 256, GSMEM>>>(ATTN, WSUM, out);
}